// round 2
// baseline (speedup 1.0000x reference)
#include <cuda_runtime.h>
#include <cstdint>
#include <math.h>

#define T      16384
#define A      128
#define KS     128
#define STEPS  16
#define EDIM   126
#define NPROB  4
#define NSLOT  256   /* T / 64 */

// ---------------- device scratch (static: no allocation) ----------------
__device__ float              g_res[NPROB * T];
__device__ float              g_dunit[A * KS];     // [atom][k]
__device__ float              g_dunitT[KS * A];    // [k][atom]
__device__ unsigned long long g_bm[NPROB * NSLOT]; // packed (value,~flat) per 64-col slot
__device__ float              g_embs[NPROB * STEPS * 128];
__device__ float              g_norm[NPROB];
__device__ int                g_slot0[NPROB];
__device__ int                g_slot1[NPROB];

// monotone float->uint mapping so packed u64 max == lexicographic (value, smaller flat idx)
__device__ __forceinline__ unsigned int fkey(float v) {
    unsigned int u = __float_as_uint(v);
    return (u & 0x80000000u) ? ~u : (u | 0x80000000u);
}
__device__ __forceinline__ float funkey(unsigned int k) {
    return (k & 0x80000000u) ? __uint_as_float(k ^ 0x80000000u) : __uint_as_float(~k);
}
__device__ __forceinline__ unsigned long long packmax(float v, unsigned int flat) {
    return ((unsigned long long)fkey(v) << 32) | (unsigned int)(~flat);
}

// ---------------- prep: copy inputs to residuals, clear block-max ----------------
__global__ void k_prep(const float* __restrict__ a, const float* __restrict__ b) {
    int i = blockIdx.x * blockDim.x + threadIdx.x;
    int n = blockDim.x * gridDim.x;
    for (int idx = i; idx < 2 * T; idx += n) {
        g_res[idx]          = a[idx];   // problems 0,1 = signal a batch 0,1
        g_res[2 * T + idx]  = b[idx];   // problems 2,3 = signal b batch 0,1
    }
    for (int idx = i; idx < NPROB * NSLOT; idx += n) g_bm[idx] = 0ull;
}

// ---------------- unit-normalized dictionary (row + transposed copies) ----------------
__global__ void k_dunit(const float* __restrict__ d) {
    int a = blockIdx.x, k = threadIdx.x;
    float v = d[a * KS + k];
    __shared__ float ssum[128];
    ssum[k] = v * v;
    __syncthreads();
    for (int off = 64; off; off >>= 1) {
        if (k < off) ssum[k] += ssum[k + off];
        __syncthreads();
    }
    float scale = 1.f / (sqrtf(ssum[0]) + 1e-8f);
    float u = v * scale;
    g_dunit[a * KS + k]  = u;
    g_dunitT[k * A + a]  = u;
}

// ---------------- correlation + per-slot block max ----------------
// Block covers COLS t-columns x 64 atoms (blockIdx.y selects atom half).
// Thread tile: 2 atoms x 8 cols, residual window slides through registers.
// INIT: full range (grid.x = 256 slots). else: window slots from g_slot0/g_slot1.
template <int COLS, bool INIT>
__global__ void __launch_bounds__(COLS * 4) k_conv() {
    constexpr int NT = COLS * 4;
    constexpr int NA = 64;
    int p  = blockIdx.z;
    int ah = blockIdx.y;
    int slot, t0;
    if (INIT) {
        slot = blockIdx.x;
        t0   = slot * 64;
    } else {
        slot = g_slot0[p] + (blockIdx.x >> 1);
        if (slot > g_slot1[p]) return;
        t0 = slot * 64 + (blockIdx.x & 1) * COLS;   // COLS = 32 here
    }

    __shared__ float d_s[KS * NA];
    __shared__ float r_s[COLS + 136];
    __shared__ unsigned long long red[NT];

    int tid   = threadIdx.x;
    int abase = ah * NA;

    for (int i = tid; i < KS * NA; i += NT) {
        int k = i >> 6, aa = i & 63;
        d_s[i] = g_dunitT[k * A + abase + aa];
    }
    for (int i = tid; i < COLS + 136; i += NT) {
        int t = t0 - 64 + i;
        r_s[i] = (t >= 0 && t < T && i < COLS + 127) ? g_res[p * T + t] : 0.f;
    }
    __syncthreads();

    int ag = tid & 31;     // 32 atom-groups of 2
    int cg = tid >> 5;     // col-groups of 8
    int lc = cg * 8;
    int a0 = 2 * ag;

    float acc0[8], acc1[8], rwin[8];
#pragma unroll
    for (int j = 0; j < 8; j++) { acc0[j] = 0.f; acc1[j] = 0.f; rwin[j] = r_s[lc + j]; }

    for (int kb = 0; kb < KS; kb += 8) {
#pragma unroll
        for (int ku = 0; ku < 8; ku++) {
            int k = kb + ku;
            float2 dd = *(const float2*)&d_s[k * NA + a0];
#pragma unroll
            for (int j = 0; j < 8; j++) {
                float rv = rwin[(ku + j) & 7];
                acc0[j] = fmaf(dd.x, rv, acc0[j]);
                acc1[j] = fmaf(dd.y, rv, acc1[j]);
            }
            rwin[ku] = r_s[lc + k + 8];
        }
    }

    unsigned long long best = 0ull;
#pragma unroll
    for (int j = 0; j < 8; j++) {
        unsigned int t = (unsigned int)(t0 + lc + j);
        unsigned int f0 = (unsigned int)(abase + a0) * (unsigned int)T + t;  // ref flat = a*T + t
        unsigned long long p0 = packmax(acc0[j], f0);
        unsigned long long p1 = packmax(acc1[j], f0 + T);
        if (p0 > best) best = p0;
        if (p1 > best) best = p1;
    }
    red[tid] = best;
    __syncthreads();
    for (int off = NT / 2; off; off >>= 1) {
        if (tid < off && red[tid + off] > red[tid]) red[tid] = red[tid + off];
        __syncthreads();
    }
    if (tid == 0) atomicMax(&g_bm[p * NSLOT + slot], red[0]);
}

// ---------------- per-step select + embedding + residual update ----------------
__global__ void k_sel(int step, const float* __restrict__ atom_emb) {
    int p = blockIdx.x;
    int tid = threadIdx.x;
    __shared__ unsigned long long red[256];
    red[tid] = g_bm[p * NSLOT + tid];
    __syncthreads();
    for (int off = 128; off; off >>= 1) {
        if (tid < off && red[tid + off] > red[tid]) red[tid] = red[tid + off];
        __syncthreads();
    }
    __shared__ float s_val;
    __shared__ int   s_ai, s_ti;
    if (tid == 0) {
        unsigned long long b = red[0];
        unsigned int flat = ~(unsigned int)(b & 0xFFFFFFFFull);
        s_val = funkey((unsigned int)(b >> 32));
        s_ai  = (int)(flat >> 14);        // T = 2^14
        s_ti  = (int)(flat & (T - 1));
    }
    __syncthreads();
    float value = s_val;
    int   ai = s_ai, ti = s_ti;

    if (tid < 128) {
        float* erow = &g_embs[(p * STEPS + step) * 128];
        if (tid == 0) {
            // forward of soft_dirac(one-hot row) == one_hot(argmax(pos_row))
            int posIdx = (value > 0.f) ? ti : ((value == 0.f) ? 0 : (ti == 0 ? 1 : 0));
            erow[0] = 20.f * (float)posIdx / (float)(T - 1);
        } else if (tid == 1) {
            erow[1] = value;
        } else {
            int atomIdx = (value > 0.f) ? ai : ((value == 0.f) ? 0 : (ai == 0 ? 1 : 0));
            erow[tid] = atom_emb[atomIdx * EDIM + tid - 2];
        }
    } else {
        int j = tid - 128;
        int t = ti - 64 + j;
        if (t >= 0 && t < T) g_res[p * T + t] -= value * g_dunit[ai * KS + j];
    }

    int s0 = (ti - 127 > 0 ? ti - 127 : 0) >> 6;
    int s1 = (ti + 127 < T - 1 ? ti + 127 : T - 1) >> 6;
    if (tid == 0) { g_slot0[p] = s0; g_slot1[p] = s1; }
    __syncthreads();   // all g_bm reads (top of kernel) are long done; safe to reset
    if (tid >= s0 && tid <= s1) g_bm[p * NSLOT + tid] = 0ull;
}

// ---------------- residual norms ----------------
__global__ void k_norm() {
    int p = blockIdx.x, tid = threadIdx.x;
    __shared__ float sh[256];
    float acc = 0.f;
    for (int i = tid; i < T; i += 256) {
        float v = g_res[p * T + i];
        acc = fmaf(v, v, acc);
    }
    sh[tid] = acc;
    __syncthreads();
    for (int off = 128; off; off >>= 1) {
        if (tid < off) sh[tid] += sh[tid + off];
        __syncthreads();
    }
    if (tid == 0) g_norm[p] = sqrtf(sh[0]);
}

// ---------------- canonical ordering + loss ----------------
__global__ void k_final(const float* __restrict__ proj, float* __restrict__ out) {
    int tid = threadIdx.x;   // 128 threads
    __shared__ float keys[NPROB][STEPS];
    __shared__ int   ord[NPROB][STEPS];
    __shared__ float pr[128];
    __shared__ float sh[128];

    pr[tid] = proj[tid];
    __syncthreads();

    if (tid < NPROB * STEPS) {
        int p = tid / STEPS, s = tid % STEPS;
        const float* e = &g_embs[(p * STEPS + s) * 128];
        float k = 0.f;
        for (int c = 0; c < 128; c++) k = fmaf(e[c], pr[c], k);
        keys[p][s] = k;
    }
    __syncthreads();
    if (tid < NPROB * STEPS) {           // stable ascending argsort via rank
        int p = tid / STEPS, s = tid % STEPS;
        float k = keys[p][s];
        int r = 0;
        for (int s2 = 0; s2 < STEPS; s2++) {
            float k2 = keys[p][s2];
            if (k2 < k || (k2 == k && s2 < s)) r++;
        }
        ord[p][r] = s;
    }
    __syncthreads();

    float acc = 0.f;
    for (int p = 0; p < 2; p++)
        for (int r = 0; r < STEPS; r++) {
            float da = g_embs[(p * STEPS + ord[p][r]) * 128 + tid]
                     - g_embs[((p + 2) * STEPS + ord[p + 2][r]) * 128 + tid];
            acc = fmaf(da, da, acc);
        }
    sh[tid] = acc;
    __syncthreads();
    for (int off = 64; off; off >>= 1) {
        if (tid < off) sh[tid] += sh[tid + off];
        __syncthreads();
    }
    if (tid == 0) {
        float l1 = sh[0] / (float)(2 * STEPS * 128);
        float l2 = 0.5f * (fabsf(g_norm[0] - g_norm[2]) + fabsf(g_norm[1] - g_norm[3]));
        out[0] = l1 + l2;
    }
}

// ---------------- launch ----------------
extern "C" void kernel_launch(void* const* d_in, const int* in_sizes, int n_in,
                              void* d_out, int out_size) {
    const float* a    = (const float*)d_in[0];
    const float* b    = (const float*)d_in[1];
    const float* d    = (const float*)d_in[2];
    const float* aemb = (const float*)d_in[3];
    const float* proj = (const float*)d_in[4];
    float* out = (float*)d_out;

    k_prep<<<64, 256>>>(a, b);
    k_dunit<<<A, 128>>>(d);
    k_conv<64, true><<<dim3(256, 2, NPROB), 256>>>();   // full correlation + slot maxima
    for (int s = 0; s < STEPS; s++) {
        k_sel<<<NPROB, 256>>>(s, aemb);
        if (s < STEPS - 1)
            k_conv<32, false><<<dim3(10, 2, NPROB), 128>>>();  // recompute touched slots
    }
    k_norm<<<NPROB, 256>>>();
    k_final<<<1, 128>>>(proj, out);
}

// round 3
// speedup vs baseline: 1.0044x; 1.0044x over previous
#include <cuda_runtime.h>
#include <cstdint>
#include <math.h>

#define T      16384
#define A      128
#define KS     128
#define STEPS  16
#define EDIM   126
#define NPROB  4
#define NHS    512            /* T / 32 half-slots */
#define NBM    (NHS * 4)      /* entries per problem: halfslot x atom-quarter */

// ---------------- device scratch (static: no allocation) ----------------
__device__ unsigned long long g_bm[2][NPROB][NBM];  // double-buffered slot maxima
__device__ float              g_dunit[A * KS];      // [atom][k]
__device__ float              g_dunitT[KS * A];     // [k][atom]
__device__ float              g_embs[NPROB * STEPS * 128];
__device__ float              g_hv[NPROB * STEPS];
__device__ int                g_hai[NPROB * STEPS];
__device__ int                g_hti[NPROB * STEPS];
__device__ float              g_norm[NPROB];

// monotone float->uint mapping so packed u64 max == lexicographic (value, smaller flat idx)
__device__ __forceinline__ unsigned int fkey(float v) {
    unsigned int u = __float_as_uint(v);
    return (u & 0x80000000u) ? ~u : (u | 0x80000000u);
}
__device__ __forceinline__ float funkey(unsigned int k) {
    return (k & 0x80000000u) ? __uint_as_float(k ^ 0x80000000u) : __uint_as_float(~k);
}
__device__ __forceinline__ unsigned long long packmax(float v, unsigned int flat) {
    return ((unsigned long long)fkey(v) << 32) | (unsigned int)(~flat);
}
__device__ __forceinline__ const float* sigptr(int p, const float* a, const float* b) {
    return p < 2 ? a + p * T : b + (p - 2) * T;
}

// ---------------- unit-normalized dictionary ----------------
__global__ void k_dunit(const float* __restrict__ d) {
    int a = blockIdx.x, k = threadIdx.x;
    float v = d[a * KS + k];
    __shared__ float ssum[128];
    ssum[k] = v * v;
    __syncthreads();
    for (int off = 64; off; off >>= 1) {
        if (k < off) ssum[k] += ssum[k + off];
        __syncthreads();
    }
    float scale = 1.f / (sqrtf(ssum[0]) + 1e-8f);
    float u = v * scale;
    g_dunit[a * KS + k] = u;
    g_dunitT[k * A + a] = u;
}

// ---------------- initial full correlation ----------------
// Block: 64 cols (one slot) x 32 atoms (one quarter). Thread tile: 2 atoms x 8 cols.
// Writes TWO g_bm entries (one per 32-col half-slot) into buffer 0.
__global__ void __launch_bounds__(128) k_conv_init(const float* __restrict__ a,
                                                   const float* __restrict__ b) {
    int slot = blockIdx.x, q = blockIdx.y, p = blockIdx.z;
    int tid = threadIdx.x;
    const float* sig = sigptr(p, a, b);
    int t0 = slot * 64;
    int abase = q * 32;

    __shared__ float d_s[KS * 32];
    __shared__ float r_s[64 + 136];
    __shared__ unsigned long long red[128];

    for (int i = tid; i < KS * 32; i += 128) {
        int k = i >> 5, aa = i & 31;
        d_s[i] = g_dunitT[k * A + abase + aa];
    }
    for (int i = tid; i < 200; i += 128) {
        int t = t0 - 64 + i;
        r_s[i] = (t >= 0 && t < T && i < 191) ? sig[t] : 0.f;
    }
    __syncthreads();

    int ag = tid & 15, cg = tid >> 4;
    int lc = cg * 8, a0 = 2 * ag;

    float acc0[8], acc1[8], rwin[8];
#pragma unroll
    for (int j = 0; j < 8; j++) { acc0[j] = 0.f; acc1[j] = 0.f; rwin[j] = r_s[lc + j]; }

    for (int kb = 0; kb < KS; kb += 8) {
#pragma unroll
        for (int ku = 0; ku < 8; ku++) {
            int k = kb + ku;
            float2 dd = *(const float2*)&d_s[k * 32 + a0];
#pragma unroll
            for (int j = 0; j < 8; j++) {
                float rv = rwin[(ku + j) & 7];
                acc0[j] = fmaf(dd.x, rv, acc0[j]);
                acc1[j] = fmaf(dd.y, rv, acc1[j]);
            }
            rwin[ku] = r_s[lc + k + 8];
        }
    }

    unsigned long long best = 0ull;
#pragma unroll
    for (int j = 0; j < 8; j++) {
        unsigned int f0 = (unsigned int)(abase + a0) * (unsigned int)T + (unsigned int)(t0 + lc + j);
        unsigned long long p0 = packmax(acc0[j], f0);
        unsigned long long p1 = packmax(acc1[j], f0 + T);
        if (p0 > best) best = p0;
        if (p1 > best) best = p1;
    }
    red[tid] = best;
    __syncthreads();
    // segmented reduce: cols 0..31 -> tids 0..63, cols 32..63 -> tids 64..127
    for (int off = 32; off; off >>= 1) {
        if ((tid & 63) < off && red[tid + off] > red[tid]) red[tid] = red[tid + off];
        __syncthreads();
    }
    if ((tid & 63) == 0) {
        int half = tid >> 6;
        g_bm[0][p][(slot * 2 + half) * 4 + q] = red[tid];
    }
}

// ---------------- fused per-step kernel ----------------
// Every block: selection over g_bm (old buffer). Block x==0 emits embedding+history.
// Blocks 0..15 copy untouched entries to the new buffer. Then each block recomputes
// one (half-slot, quarter) of the window: 32 cols x 32 atoms, tile 1 atom x 8 cols.
__global__ void __launch_bounds__(128) k_step(int step,
                                              const float* __restrict__ a,
                                              const float* __restrict__ b,
                                              const float* __restrict__ aemb) {
    int p = blockIdx.y, bx = blockIdx.x, tid = threadIdx.x;
    const unsigned long long* bufR = g_bm[step & 1][p];
    unsigned long long*       bufW = g_bm[(step + 1) & 1][p];
    const float* sig = sigptr(p, a, b);

    __shared__ unsigned long long red[128];
    __shared__ float s_val;
    __shared__ int   s_ai, s_ti, s_h0, s_h1;

    // ---- selection (redundant per block, deterministic) ----
    unsigned long long vals[16], best = 0ull;
#pragma unroll
    for (int i = 0; i < 16; i++) {
        vals[i] = bufR[tid + 128 * i];
        if (vals[i] > best) best = vals[i];
    }
    red[tid] = best;
    __syncthreads();
    for (int off = 64; off; off >>= 1) {
        if (tid < off && red[tid + off] > red[tid]) red[tid] = red[tid + off];
        __syncthreads();
    }
    if (tid == 0) {
        unsigned long long bm = red[0];
        unsigned int flat = ~(unsigned int)(bm & 0xFFFFFFFFull);
        s_val = funkey((unsigned int)(bm >> 32));
        s_ai  = (int)(flat >> 14);
        s_ti  = (int)(flat & (T - 1));
        int lo = s_ti - 127; if (lo < 0) lo = 0;
        int hi = s_ti + 127; if (hi > T - 1) hi = T - 1;
        s_h0 = lo >> 5;
        s_h1 = hi >> 5;
    }
    __syncthreads();
    float value = s_val;
    int   ai = s_ai, ti = s_ti, h0 = s_h0, h1 = s_h1;

    // ---- embedding + history (designated block) ----
    if (bx == 0) {
        float* erow = &g_embs[(p * STEPS + step) * 128];
        if (tid == 0) {
            int posIdx = (value > 0.f) ? ti : ((value == 0.f) ? 0 : (ti == 0 ? 1 : 0));
            erow[0] = 20.f * (float)posIdx / (float)(T - 1);
            g_hv[p * STEPS + step]  = value;
            g_hai[p * STEPS + step] = ai;
            g_hti[p * STEPS + step] = ti;
        } else if (tid == 1) {
            erow[1] = value;
        } else {
            int atomIdx = (value > 0.f) ? ai : ((value == 0.f) ? 0 : (ai == 0 ? 1 : 0));
            erow[tid] = aemb[atomIdx * EDIM + tid - 2];
        }
    }
    if (step == STEPS - 1) return;   // last step: selection + emit only

    // ---- carry over untouched entries to new buffer ----
    if (bx < 16) {
        int e = bx * 128 + tid;
        int hs = e >> 2;
        if (hs < h0 || hs > h1) bufW[e] = vals[bx];
    }

    // ---- window re-correlation ----
    int hs = h0 + (bx >> 2);
    if (hs > h1) return;             // block-uniform exit
    int q = bx & 3;
    int t0 = hs * 32, abase = q * 32;

    __shared__ float d_s[KS * 32];
    __shared__ float r_s[32 + 136];

    for (int i = tid; i < KS * 32; i += 128) {
        int k = i >> 5, aa = i & 31;
        d_s[i] = g_dunitT[k * A + abase + aa];
    }
    for (int i = tid; i < 168; i += 128) {
        int t = t0 - 64 + i;
        float r = 0.f;
        if (t >= 0 && t < T && i < 159) {
            r = sig[t];
            for (int h = 0; h <= step; h++) {
                float vh; int aih, tih;
                if (h == step) { vh = value; aih = ai; tih = ti; }
                else {
                    vh  = g_hv[p * STEPS + h];
                    aih = g_hai[p * STEPS + h];
                    tih = g_hti[p * STEPS + h];
                }
                int j = t - tih + 64;
                if (j >= 0 && j < KS) r -= vh * g_dunit[aih * KS + j];
            }
        }
        r_s[i] = r;
    }
    __syncthreads();

    int ag = tid & 31, cg = tid >> 5;
    int lc = cg * 8, a0 = ag;

    float acc[8], rwin[8];
#pragma unroll
    for (int j = 0; j < 8; j++) { acc[j] = 0.f; rwin[j] = r_s[lc + j]; }

    for (int kb = 0; kb < KS; kb += 8) {
#pragma unroll
        for (int ku = 0; ku < 8; ku++) {
            int k = kb + ku;
            float dv = d_s[k * 32 + a0];
#pragma unroll
            for (int j = 0; j < 8; j++)
                acc[j] = fmaf(dv, rwin[(ku + j) & 7], acc[j]);
            rwin[ku] = r_s[lc + k + 8];
        }
    }

    unsigned long long b2 = 0ull;
#pragma unroll
    for (int j = 0; j < 8; j++) {
        unsigned int f = (unsigned int)(abase + a0) * (unsigned int)T + (unsigned int)(t0 + lc + j);
        unsigned long long pm = packmax(acc[j], f);
        if (pm > b2) b2 = pm;
    }
    __syncthreads();   // red[] reuse safe
    red[tid] = b2;
    __syncthreads();
    for (int off = 64; off; off >>= 1) {
        if (tid < off && red[tid + off] > red[tid]) red[tid] = red[tid + off];
        __syncthreads();
    }
    if (tid == 0) bufW[hs * 4 + q] = red[0];
}

// ---------------- residual norms (reconstructed from history) ----------------
__global__ void k_norm(const float* __restrict__ a, const float* __restrict__ b) {
    int p = blockIdx.x, tid = threadIdx.x;   // 256 threads
    __shared__ float sv[STEPS];
    __shared__ int   sai[STEPS], sti[STEPS];
    __shared__ float sh[256];
    if (tid < STEPS) {
        sv[tid]  = g_hv[p * STEPS + tid];
        sai[tid] = g_hai[p * STEPS + tid];
        sti[tid] = g_hti[p * STEPS + tid];
    }
    __syncthreads();
    const float* sig = sigptr(p, a, b);
    float acc = 0.f;
    for (int t = tid; t < T; t += 256) {
        float r = sig[t];
        for (int h = 0; h < STEPS; h++) {
            int j = t - sti[h] + 64;
            if (j >= 0 && j < KS) r -= sv[h] * g_dunit[sai[h] * KS + j];
        }
        acc = fmaf(r, r, acc);
    }
    sh[tid] = acc;
    __syncthreads();
    for (int off = 128; off; off >>= 1) {
        if (tid < off) sh[tid] += sh[tid + off];
        __syncthreads();
    }
    if (tid == 0) g_norm[p] = sqrtf(sh[0]);
}

// ---------------- canonical ordering + loss ----------------
__global__ void k_final(const float* __restrict__ proj, float* __restrict__ out) {
    int tid = threadIdx.x;   // 128 threads
    __shared__ float keys[NPROB][STEPS];
    __shared__ int   ord[NPROB][STEPS];
    __shared__ float pr[128];
    __shared__ float sh[128];

    pr[tid] = proj[tid];
    __syncthreads();

    if (tid < NPROB * STEPS) {
        int p = tid / STEPS, s = tid % STEPS;
        const float* e = &g_embs[(p * STEPS + s) * 128];
        float k = 0.f;
        for (int c = 0; c < 128; c++) k = fmaf(e[c], pr[c], k);
        keys[p][s] = k;
    }
    __syncthreads();
    if (tid < NPROB * STEPS) {
        int p = tid / STEPS, s = tid % STEPS;
        float k = keys[p][s];
        int r = 0;
        for (int s2 = 0; s2 < STEPS; s2++) {
            float k2 = keys[p][s2];
            if (k2 < k || (k2 == k && s2 < s)) r++;
        }
        ord[p][r] = s;
    }
    __syncthreads();

    float acc = 0.f;
    for (int p = 0; p < 2; p++)
        for (int r = 0; r < STEPS; r++) {
            float da = g_embs[(p * STEPS + ord[p][r]) * 128 + tid]
                     - g_embs[((p + 2) * STEPS + ord[p + 2][r]) * 128 + tid];
            acc = fmaf(da, da, acc);
        }
    sh[tid] = acc;
    __syncthreads();
    for (int off = 64; off; off >>= 1) {
        if (tid < off) sh[tid] += sh[tid + off];
        __syncthreads();
    }
    if (tid == 0) {
        float l1 = sh[0] / (float)(2 * STEPS * 128);
        float l2 = 0.5f * (fabsf(g_norm[0] - g_norm[2]) + fabsf(g_norm[1] - g_norm[3]));
        out[0] = l1 + l2;
    }
}

// ---------------- launch ----------------
extern "C" void kernel_launch(void* const* d_in, const int* in_sizes, int n_in,
                              void* d_out, int out_size) {
    const float* a    = (const float*)d_in[0];
    const float* b    = (const float*)d_in[1];
    const float* d    = (const float*)d_in[2];
    const float* aemb = (const float*)d_in[3];
    const float* proj = (const float*)d_in[4];
    float* out = (float*)d_out;

    k_dunit<<<A, 128>>>(d);
    k_conv_init<<<dim3(256, 4, NPROB), 128>>>(a, b);
    for (int s = 0; s < STEPS; s++) {
        int nbx = (s < STEPS - 1) ? 36 : 1;   // 9 half-slots x 4 quarters
        k_step<<<dim3(nbx, NPROB), 128>>>(s, a, b, aemb);
    }
    k_norm<<<NPROB, 256>>>(a, b);
    k_final<<<1, 128>>>(proj, out);
}

// round 10
// speedup vs baseline: 1.0241x; 1.0196x over previous
#include <cuda_runtime.h>
#include <cstdint>
#include <math.h>

#define T      16384
#define A      128
#define KS     128
#define STEPS  16
#define EDIM   126
#define NPROB  4
#define NBM    2048           /* entries per problem: 512 half-slots x 4 atom-quarters */
#define NBLK   36             /* blocks per problem */

typedef unsigned long long u64;

// ---------------- device scratch (static: no allocation) ----------------
__device__ u64   g_bm[2][NPROB][NBM];     // double-buffered slot maxima
__device__ float g_dunit[A * KS];         // [atom][k]
__device__ float g_dunitT[KS * A];        // [k][atom]
__device__ float g_embs[NPROB * STEPS * 128];
__device__ float g_part[NPROB][32];
__device__ int   g_flag[NPROB * (STEPS + 1) * NBLK];   // per-problem step barriers
__device__ int   g_gflag[160];                          // global final barrier

// ---------------- helpers ----------------
__device__ __forceinline__ unsigned int fkey(float v) {
    unsigned int u = __float_as_uint(v);
    return (u & 0x80000000u) ? ~u : (u | 0x80000000u);
}
__device__ __forceinline__ float funkey(unsigned int k) {
    return (k & 0x80000000u) ? __uint_as_float(k ^ 0x80000000u) : __uint_as_float(~k);
}
__device__ __forceinline__ u64 packmax(float v, unsigned int flat) {
    return ((u64)fkey(v) << 32) | (unsigned int)(~flat);
}
__device__ __forceinline__ const float* sigptr(int p, const float* a, const float* b) {
    return p < 2 ? a + p * T : b + (p - 2) * T;
}

// ---- L2-coherent accesses: every cross-block byte moves through L2 ----
__device__ __forceinline__ u64 ldcg_u64(const u64* p) {
    u64 v; asm volatile("ld.global.cg.b64 %0, [%1];" : "=l"(v) : "l"(p)); return v;
}
__device__ __forceinline__ float ldcg_f32(const float* p) {
    float v; asm volatile("ld.global.cg.f32 %0, [%1];" : "=f"(v) : "l"(p)); return v;
}
__device__ __forceinline__ void stcg_u64(u64* p, u64 v) {
    asm volatile("st.global.cg.b64 [%0], %1;" :: "l"(p), "l"(v) : "memory");
}
__device__ __forceinline__ void stcg_f32(float* p, float v) {
    asm volatile("st.global.cg.f32 [%0], %1;" :: "l"(p), "f"(v) : "memory");
}
// ---- release/acquire flag protocol ----
__device__ __forceinline__ void st_release(int* p, int v) {
    asm volatile("st.release.gpu.global.s32 [%0], %1;" :: "l"(p), "r"(v) : "memory");
}
__device__ __forceinline__ int ld_acquire(const int* p) {
    int v; asm volatile("ld.acquire.gpu.global.s32 %0, [%1];" : "=r"(v) : "l"(p) : "memory");
    return v;
}
__device__ __forceinline__ void barrier_arrive(int* flag) {
    __syncthreads();                 // all block threads' stores issued
    __threadfence();                 // every thread fences its own stores to GPU scope
    if (threadIdx.x == 0) st_release(flag, 1);
}
__device__ __forceinline__ void barrier_wait(const int* flags, int n) {
    for (int f = threadIdx.x; f < n; f += blockDim.x)
        while (ld_acquire(&flags[f]) == 0) {}
    __threadfence();
    __syncthreads();
}

// ---------------- unit-normalized dictionary + barrier reset ----------------
__global__ void k_dunit(const float* __restrict__ d) {
    int a = blockIdx.x, k = threadIdx.x;
    int gi = blockIdx.x * 128 + threadIdx.x;
    if (gi < NPROB * (STEPS + 1) * NBLK) g_flag[gi] = 0;
    if (gi < 160) g_gflag[gi] = 0;

    float v = d[a * KS + k];
    __shared__ float ssum[128];
    ssum[k] = v * v;
    __syncthreads();
    for (int off = 64; off; off >>= 1) {
        if (k < off) ssum[k] += ssum[k + off];
        __syncthreads();
    }
    float scale = 1.f / (sqrtf(ssum[0]) + 1e-8f);
    float u = v * scale;
    g_dunit[a * KS + k] = u;
    g_dunitT[k * A + a] = u;
}

// ---------------- persistent pursuit kernel ----------------
__global__ void __launch_bounds__(128) k_persist(const float* __restrict__ a,
                                                 const float* __restrict__ b,
                                                 const float* __restrict__ aemb,
                                                 const float* __restrict__ proj,
                                                 float* __restrict__ out) {
    int p  = blockIdx.x / NBLK;
    int bx = blockIdx.x % NBLK;
    int q  = bx & 3;          // atom quarter
    int wr = bx >> 2;         // window row 0..8
    int tid = threadIdx.x;
    const float* sig = sigptr(p, a, b);
    int* flags = &g_flag[p * (STEPS + 1) * NBLK];

    __shared__ float d_s[KS * 32];    // quarter dict [k][a]
    __shared__ float r_s[200];        // residual window
    __shared__ u64   red[128];
    __shared__ float shf[128];
    __shared__ float sv[STEPS];
    __shared__ int   sai[STEPS], sti[STEPS];
    __shared__ float s_val;
    __shared__ int   s_ai, s_ti, s_h0, s_h1;
    __shared__ float keys[NPROB][STEPS];
    __shared__ int   ord[NPROB][STEPS];
    __shared__ float snorm[NPROB];

    int abase = q * 32;
    for (int i = tid; i < KS * 32; i += 128) {
        int k = i >> 5, aa = i & 31;
        d_s[i] = g_dunitT[k * A + abase + aa];
    }
    // (first init slot's __syncthreads covers d_s visibility)

    // ================= INIT: full correlation over assigned slots =================
    // (identical math/order to the Round-3 passing k_conv_init)
    {
        int ag = tid & 15, cg = tid >> 4;
        int lc = cg * 8, a0 = 2 * ag;
        for (int slot = wr; slot < 256; slot += 9) {
            int t0 = slot * 64;
            __syncthreads();   // r_s safe to overwrite
            for (int i = tid; i < 200; i += 128) {
                int t = t0 - 64 + i;
                r_s[i] = (t >= 0 && t < T && i < 191) ? sig[t] : 0.f;
            }
            __syncthreads();

            float acc0[8], acc1[8], rwin[8];
#pragma unroll
            for (int j = 0; j < 8; j++) { acc0[j] = 0.f; acc1[j] = 0.f; rwin[j] = r_s[lc + j]; }
            for (int kb = 0; kb < KS; kb += 8) {
#pragma unroll
                for (int ku = 0; ku < 8; ku++) {
                    int k = kb + ku;
                    float2 dd = *(const float2*)&d_s[k * 32 + a0];
#pragma unroll
                    for (int j = 0; j < 8; j++) {
                        float rv = rwin[(ku + j) & 7];
                        acc0[j] = fmaf(dd.x, rv, acc0[j]);
                        acc1[j] = fmaf(dd.y, rv, acc1[j]);
                    }
                    rwin[ku] = r_s[lc + k + 8];
                }
            }
            u64 best = 0ull;
#pragma unroll
            for (int j = 0; j < 8; j++) {
                unsigned int f0 = (unsigned int)(abase + a0) * (unsigned int)T
                                + (unsigned int)(t0 + lc + j);
                u64 p0 = packmax(acc0[j], f0);
                u64 p1 = packmax(acc1[j], f0 + T);
                if (p0 > best) best = p0;
                if (p1 > best) best = p1;
            }
            red[tid] = best;
            __syncthreads();
            for (int off = 32; off; off >>= 1) {
                if ((tid & 63) < off && red[tid + off] > red[tid]) red[tid] = red[tid + off];
                __syncthreads();
            }
            if ((tid & 63) == 0)
                stcg_u64(&g_bm[0][p][(slot * 2 + (tid >> 6)) * 4 + q], red[tid]);
        }
    }
    barrier_arrive(&flags[STEPS * NBLK + bx]);
    barrier_wait(&flags[STEPS * NBLK], NBLK);

    // ================= STEP LOOP =================
    for (int s = 0; s < STEPS; s++) {
        const u64* bufR = g_bm[s & 1][p];
        u64*       bufW = g_bm[(s + 1) & 1][p];

        // ---- selection (redundant per block; L2-coherent loads) ----
        u64 vals[16], best = 0ull;
#pragma unroll
        for (int i = 0; i < 16; i++) {
            vals[i] = ldcg_u64(&bufR[tid + 128 * i]);
            if (vals[i] > best) best = vals[i];
        }
        red[tid] = best;
        __syncthreads();
        for (int off = 64; off; off >>= 1) {
            if (tid < off && red[tid + off] > red[tid]) red[tid] = red[tid + off];
            __syncthreads();
        }
        if (tid == 0) {
            u64 bm = red[0];
            unsigned int flat = ~(unsigned int)(bm & 0xFFFFFFFFull);
            s_val = funkey((unsigned int)(bm >> 32));
            s_ai  = (int)(flat >> 14);
            s_ti  = (int)(flat & (T - 1));
            int lo = s_ti - 127; if (lo < 0) lo = 0;
            int hi = s_ti + 127; if (hi > T - 1) hi = T - 1;
            s_h0 = lo >> 5;  s_h1 = hi >> 5;
            sv[s] = s_val; sai[s] = s_ai; sti[s] = s_ti;
        }
        __syncthreads();
        float value = s_val;
        int ai = s_ai, ti = s_ti, h0 = s_h0, h1 = s_h1;

        if (bx == 0) {
            float* erow = &g_embs[(p * STEPS + s) * 128];
            if (tid == 0) {
                int posIdx = (value > 0.f) ? ti : ((value == 0.f) ? 0 : (ti == 0 ? 1 : 0));
                stcg_f32(&erow[0], 20.f * (float)posIdx / (float)(T - 1));
            } else if (tid == 1) {
                stcg_f32(&erow[1], value);
            } else {
                int atomIdx = (value > 0.f) ? ai : ((value == 0.f) ? 0 : (ai == 0 ? 1 : 0));
                stcg_f32(&erow[tid], aemb[atomIdx * EDIM + tid - 2]);
            }
        }

        if (s < STEPS - 1) {
            // ---- carry untouched entries ----
            if (bx < 16) {
                int e = bx * 128 + tid;
                int hs = e >> 2;
                if (hs < h0 || hs > h1) stcg_u64(&bufW[e], vals[bx]);
            }
            // ---- window re-correlation (Round-3 proven scalar form) ----
            int hs = h0 + wr;
            if (hs <= h1) {                     // block-uniform
                int t0 = hs * 32;
                __syncthreads();                // r_s reuse safe
                for (int i = tid; i < 168; i += 128) {
                    int t = t0 - 64 + i;
                    float r = 0.f;
                    if (t >= 0 && t < T && i < 159) {
                        r = sig[t];
                        for (int h = 0; h <= s; h++) {
                            int j = t - sti[h] + 64;
                            if ((unsigned)j < 128u) r -= sv[h] * g_dunit[sai[h] * KS + j];
                        }
                    }
                    r_s[i] = r;
                }
                __syncthreads();

                int ag = tid & 31, cg = tid >> 5;
                int lc = cg * 8, a0 = ag;
                float acc[8], rwin[8];
#pragma unroll
                for (int j = 0; j < 8; j++) { acc[j] = 0.f; rwin[j] = r_s[lc + j]; }
                for (int kb = 0; kb < KS; kb += 8) {
#pragma unroll
                    for (int ku = 0; ku < 8; ku++) {
                        int k = kb + ku;
                        float dv = d_s[k * 32 + a0];
#pragma unroll
                        for (int j = 0; j < 8; j++)
                            acc[j] = fmaf(dv, rwin[(ku + j) & 7], acc[j]);
                        rwin[ku] = r_s[lc + k + 8];
                    }
                }
                u64 b2 = 0ull;
#pragma unroll
                for (int j = 0; j < 8; j++) {
                    unsigned int f = (unsigned int)(abase + a0) * (unsigned int)T
                                   + (unsigned int)(t0 + lc + j);
                    u64 pm = packmax(acc[j], f);
                    if (pm > b2) b2 = pm;
                }
                __syncthreads();
                red[tid] = b2;
                __syncthreads();
                for (int off = 64; off; off >>= 1) {
                    if (tid < off && red[tid + off] > red[tid]) red[tid] = red[tid + off];
                    __syncthreads();
                }
                if (tid == 0) stcg_u64(&bufW[hs * 4 + q], red[0]);
            }
            barrier_arrive(&flags[s * NBLK + bx]);
            barrier_wait(&flags[s * NBLK], NBLK);
        }
    }

    // ================= residual-norm partials =================
    if (bx < 32) {
        int base = bx * 512;
        float acc = 0.f;
        for (int t = base + tid; t < base + 512; t += 128) {
            float r = sig[t];
#pragma unroll
            for (int h = 0; h < STEPS; h++) {
                int j = t - sti[h] + 64;
                if ((unsigned)j < 128u) r -= sv[h] * g_dunit[sai[h] * KS + j];
            }
            acc = fmaf(r, r, acc);
        }
        shf[tid] = acc;
        __syncthreads();
        for (int off = 64; off; off >>= 1) {
            if (tid < off) shf[tid] += shf[tid + off];
            __syncthreads();
        }
        if (tid == 0) stcg_f32(&g_part[p][bx], shf[0]);
    }

    // ================= global barrier + final loss =================
    __syncthreads();
    __threadfence();
    if (tid == 0) st_release(&g_gflag[blockIdx.x], 1);
    if (blockIdx.x != 0) return;

    for (int f = tid; f < NBLK * NPROB; f += 128)
        while (ld_acquire(&g_gflag[f]) == 0) {}
    __threadfence();
    __syncthreads();

    // norms
    if (tid < NPROB) {
        float sum = 0.f;
        for (int i = 0; i < 32; i++) sum += ldcg_f32(&g_part[tid][i]);
        snorm[tid] = sqrtf(sum);
    }
    // ordering keys
    shf[tid] = proj[tid];
    __syncthreads();
    if (tid < NPROB * STEPS) {
        int pp = tid / STEPS, ss = tid % STEPS;
        const float* e = &g_embs[(pp * STEPS + ss) * 128];
        float k = 0.f;
        for (int c = 0; c < 128; c++) k = fmaf(ldcg_f32(&e[c]), shf[c], k);
        keys[pp][ss] = k;
    }
    __syncthreads();
    if (tid < NPROB * STEPS) {
        int pp = tid / STEPS, ss = tid % STEPS;
        float k = keys[pp][ss];
        int r = 0;
        for (int s2 = 0; s2 < STEPS; s2++) {
            float k2 = keys[pp][s2];
            if (k2 < k || (k2 == k && s2 < ss)) r++;
        }
        ord[pp][r] = ss;
    }
    __syncthreads();

    float acc = 0.f;
    for (int pp = 0; pp < 2; pp++)
        for (int r = 0; r < STEPS; r++) {
            float da = ldcg_f32(&g_embs[(pp * STEPS + ord[pp][r]) * 128 + tid])
                     - ldcg_f32(&g_embs[((pp + 2) * STEPS + ord[pp + 2][r]) * 128 + tid]);
            acc = fmaf(da, da, acc);
        }
    __syncthreads();
    shf[tid] = acc;
    __syncthreads();
    for (int off = 64; off; off >>= 1) {
        if (tid < off) shf[tid] += shf[tid + off];
        __syncthreads();
    }
    if (tid == 0) {
        float l1 = shf[0] / (float)(2 * STEPS * 128);
        float l2 = 0.5f * (fabsf(snorm[0] - snorm[2]) + fabsf(snorm[1] - snorm[3]));
        out[0] = l1 + l2;
    }
}

// ---------------- launch ----------------
extern "C" void kernel_launch(void* const* d_in, const int* in_sizes, int n_in,
                              void* d_out, int out_size) {
    const float* a    = (const float*)d_in[0];
    const float* b    = (const float*)d_in[1];
    const float* d    = (const float*)d_in[2];
    const float* aemb = (const float*)d_in[3];
    const float* proj = (const float*)d_in[4];
    float* out = (float*)d_out;

    k_dunit<<<A, 128>>>(d);
    k_persist<<<NPROB * NBLK, 128>>>(a, b, aemb, proj, out);
}

// round 13
// speedup vs baseline: 1.0965x; 1.0707x over previous
#include <cuda_runtime.h>
#include <cstdint>
#include <math.h>

#define T      16384
#define A      128
#define KS     128
#define STEPS  16
#define EDIM   126
#define NPROB  4
#define NBM    2048           /* entries per problem: 512 half-slots x 4 atom-quarters */
#define NBLK   36             /* blocks per problem */
#define NTHR   256

typedef unsigned long long u64;

// ---------------- device scratch (static: no allocation) ----------------
__device__ u64   g_bm[2][NPROB][NBM];     // double-buffered slot maxima
__device__ float g_dunit[A * KS];         // [atom][k]
__device__ float g_dunitT[KS * A];        // [k][atom]
__device__ float g_embs[NPROB * STEPS * 128];
__device__ float g_part[NPROB][32];
__device__ int   g_flag[NPROB * (STEPS + 1) * NBLK];   // per-problem step barriers
__device__ int   g_gflag[160];                          // global final barrier

// ---------------- helpers ----------------
__device__ __forceinline__ unsigned int fkey(float v) {
    unsigned int u = __float_as_uint(v);
    return (u & 0x80000000u) ? ~u : (u | 0x80000000u);
}
__device__ __forceinline__ float funkey(unsigned int k) {
    return (k & 0x80000000u) ? __uint_as_float(k ^ 0x80000000u) : __uint_as_float(~k);
}
__device__ __forceinline__ u64 packmax(float v, unsigned int flat) {
    return ((u64)fkey(v) << 32) | (unsigned int)(~flat);
}
__device__ __forceinline__ const float* sigptr(int p, const float* a, const float* b) {
    return p < 2 ? a + p * T : b + (p - 2) * T;
}
__device__ __forceinline__ u64 warpmax(u64 v) {
#pragma unroll
    for (int o = 16; o; o >>= 1) {
        u64 w = __shfl_xor_sync(0xffffffffu, v, o);
        if (w > v) v = w;
    }
    return v;
}

// ---- L2-coherent accesses: every cross-block byte moves through L2 ----
__device__ __forceinline__ u64 ldcg_u64(const u64* p) {
    u64 v; asm volatile("ld.global.cg.b64 %0, [%1];" : "=l"(v) : "l"(p)); return v;
}
__device__ __forceinline__ float ldcg_f32(const float* p) {
    float v; asm volatile("ld.global.cg.f32 %0, [%1];" : "=f"(v) : "l"(p)); return v;
}
__device__ __forceinline__ void stcg_u64(u64* p, u64 v) {
    asm volatile("st.global.cg.b64 [%0], %1;" :: "l"(p), "l"(v) : "memory");
}
__device__ __forceinline__ void stcg_f32(float* p, float v) {
    asm volatile("st.global.cg.f32 [%0], %1;" :: "l"(p), "f"(v) : "memory");
}
// ---- release/acquire flag protocol ----
__device__ __forceinline__ void st_release(int* p, int v) {
    asm volatile("st.release.gpu.global.s32 [%0], %1;" :: "l"(p), "r"(v) : "memory");
}
__device__ __forceinline__ int ld_acquire(const int* p) {
    int v; asm volatile("ld.acquire.gpu.global.s32 %0, [%1];" : "=r"(v) : "l"(p) : "memory");
    return v;
}
__device__ __forceinline__ void barrier_arrive(int* flag) {
    __syncthreads();
    __threadfence();
    if (threadIdx.x == 0) st_release(flag, 1);
}
__device__ __forceinline__ void barrier_wait(const int* flags, int n) {
    for (int f = threadIdx.x; f < n; f += blockDim.x)
        while (ld_acquire(&flags[f]) == 0) {}
    __threadfence();
    __syncthreads();
}

// ---------------- unit-normalized dictionary + barrier reset ----------------
__global__ void k_dunit(const float* __restrict__ d) {
    int a = blockIdx.x, k = threadIdx.x;
    int gi = blockIdx.x * 128 + threadIdx.x;
    if (gi < NPROB * (STEPS + 1) * NBLK) g_flag[gi] = 0;
    if (gi < 160) g_gflag[gi] = 0;

    float v = d[a * KS + k];
    __shared__ float ssum[128];
    ssum[k] = v * v;
    __syncthreads();
    for (int off = 64; off; off >>= 1) {
        if (k < off) ssum[k] += ssum[k + off];
        __syncthreads();
    }
    float scale = 1.f / (sqrtf(ssum[0]) + 1e-8f);
    float u = v * scale;
    g_dunit[a * KS + k] = u;
    g_dunitT[k * A + a] = u;
}

// ---------------- persistent pursuit kernel ----------------
__global__ void __launch_bounds__(NTHR) k_persist(const float* __restrict__ a,
                                                  const float* __restrict__ b,
                                                  const float* __restrict__ aemb,
                                                  const float* __restrict__ proj,
                                                  float* __restrict__ out) {
    int p  = blockIdx.x / NBLK;
    int bx = blockIdx.x % NBLK;
    int q  = bx & 3;          // atom quarter
    int wr = bx >> 2;         // window row 0..8
    int tid  = threadIdx.x;
    int lane = tid & 31, warp = tid >> 5;
    int hh = tid >> 7;        // half-block 0/1
    int wt = tid & 127;       // tid within half
    const float* sig = sigptr(p, a, b);
    int* flags = &g_flag[p * (STEPS + 1) * NBLK];

    __shared__ float d_s[KS * 32];    // quarter dict [k][a]
    __shared__ float r_s[2][200];     // residual windows (one per half-block)
    __shared__ u64   wred[8];
    __shared__ float shf[NTHR];
    __shared__ float sv[STEPS];
    __shared__ int   sai[STEPS], sti[STEPS];
    __shared__ float s_val;
    __shared__ int   s_ai, s_ti, s_h0, s_h1;
    __shared__ float keys[NPROB][STEPS];
    __shared__ int   ord[NPROB][STEPS];
    __shared__ float snorm[NPROB];

    int abase = q * 32;
    for (int i = tid; i < KS * 32; i += NTHR) {
        int k = i >> 5, aa = i & 31;
        d_s[i] = g_dunitT[k * A + abase + aa];
    }

    // ================= INIT: full correlation, 2 slots per iteration =================
    // thread tile (per 128-thread half): 2 atoms x 8 cols, k-serial (bit-identical to R10)
    {
        int ag = wt & 15, cg = wt >> 4;
        int lc = cg * 8, a0 = 2 * ag;
        for (int it = 0; it < 15; it++) {
            int slot = it * 18 + wr * 2 + hh;
            bool act = slot < 256;
            int t0 = slot * 64;
            __syncthreads();   // r_s / wred safe to overwrite
            if (act) {
                for (int i = wt; i < 200; i += 128) {
                    int t = t0 - 64 + i;
                    r_s[hh][i] = (t >= 0 && t < T && i < 191) ? sig[t] : 0.f;
                }
            }
            __syncthreads();

            u64 best = 0ull;
            if (act) {
                float acc0[8], acc1[8], rwin[8];
#pragma unroll
                for (int j = 0; j < 8; j++) { acc0[j] = 0.f; acc1[j] = 0.f; rwin[j] = r_s[hh][lc + j]; }
                for (int kb = 0; kb < KS; kb += 8) {
#pragma unroll
                    for (int ku = 0; ku < 8; ku++) {
                        int k = kb + ku;
                        float2 dd = *(const float2*)&d_s[k * 32 + a0];
#pragma unroll
                        for (int j = 0; j < 8; j++) {
                            float rv = rwin[(ku + j) & 7];
                            acc0[j] = fmaf(dd.x, rv, acc0[j]);
                            acc1[j] = fmaf(dd.y, rv, acc1[j]);
                        }
                        rwin[ku] = r_s[hh][lc + k + 8];
                    }
                }
#pragma unroll
                for (int j = 0; j < 8; j++) {
                    unsigned int f0 = (unsigned int)(abase + a0) * (unsigned int)T
                                    + (unsigned int)(t0 + lc + j);
                    u64 p0 = packmax(acc0[j], f0);
                    u64 p1 = packmax(acc1[j], f0 + T);
                    if (p0 > best) best = p0;
                    if (p1 > best) best = p1;
                }
            }
            best = warpmax(best);
            if (lane == 0) wred[warp] = best;   // warp covers 16 cols of its half
            __syncthreads();
            if (tid < 4) {                      // (half, segment) pairs
                int h2 = tid >> 1, seg = tid & 1;
                int sl = it * 18 + wr * 2 + h2;
                if (sl < 256) {
                    u64 m = wred[h2 * 4 + seg * 2];
                    u64 m2 = wred[h2 * 4 + seg * 2 + 1];
                    if (m2 > m) m = m2;
                    stcg_u64(&g_bm[0][p][(sl * 2 + seg) * 4 + q], m);
                }
            }
        }
    }
    barrier_arrive(&flags[STEPS * NBLK + bx]);
    barrier_wait(&flags[STEPS * NBLK], NBLK);

    // ================= STEP LOOP =================
    for (int s = 0; s < STEPS; s++) {
        const u64* bufR = g_bm[s & 1][p];
        u64*       bufW = g_bm[(s + 1) & 1][p];

        // ---- selection (redundant per block; shuffle reduce) ----
        u64 vals[8], best = 0ull;
#pragma unroll
        for (int i = 0; i < 8; i++) {
            vals[i] = ldcg_u64(&bufR[tid + NTHR * i]);
            if (vals[i] > best) best = vals[i];
        }
        best = warpmax(best);
        if (lane == 0) wred[warp] = best;
        __syncthreads();
        if (tid < 32) {
            u64 v = (tid < 8) ? wred[tid] : 0ull;
            v = warpmax(v);
            if (tid == 0) {
                unsigned int flat = ~(unsigned int)(v & 0xFFFFFFFFull);
                s_val = funkey((unsigned int)(v >> 32));
                s_ai  = (int)(flat >> 14);
                s_ti  = (int)(flat & (T - 1));
                int lo = s_ti - 127; if (lo < 0) lo = 0;
                int hi = s_ti + 127; if (hi > T - 1) hi = T - 1;
                s_h0 = lo >> 5;  s_h1 = hi >> 5;
                sv[s] = s_val; sai[s] = s_ai; sti[s] = s_ti;
            }
        }
        __syncthreads();
        float value = s_val;
        int ai = s_ai, ti = s_ti, h0 = s_h0, h1 = s_h1;

        if (bx == 0 && tid < 128) {
            float* erow = &g_embs[(p * STEPS + s) * 128];
            if (tid == 0) {
                int posIdx = (value > 0.f) ? ti : ((value == 0.f) ? 0 : (ti == 0 ? 1 : 0));
                stcg_f32(&erow[0], 20.f * (float)posIdx / (float)(T - 1));
            } else if (tid == 1) {
                stcg_f32(&erow[1], value);
            } else {
                int atomIdx = (value > 0.f) ? ai : ((value == 0.f) ? 0 : (ai == 0 ? 1 : 0));
                stcg_f32(&erow[tid], aemb[atomIdx * EDIM + tid - 2]);
            }
        }

        if (s < STEPS - 1) {
            // ---- carry untouched entries ----
            if (bx < 8) {
                int e = bx * NTHR + tid;
                int hs = e >> 2;
                if (hs < h0 || hs > h1) stcg_u64(&bufW[e], vals[bx]);
            }
            // ---- window re-correlation: 32 cols x 32 atoms, 4 cols x 1 atom / thread ----
            int hs = h0 + wr;
            if (hs <= h1) {                     // block-uniform
                int t0 = hs * 32;
                for (int i = tid; i < 168; i += NTHR) {
                    int t = t0 - 64 + i;
                    float r = 0.f;
                    if (t >= 0 && t < T && i < 159) {
                        r = sig[t];
                        for (int h = 0; h <= s; h++) {
                            int j = t - sti[h] + 64;
                            if ((unsigned)j < 128u) r -= sv[h] * g_dunit[sai[h] * KS + j];
                        }
                    }
                    r_s[0][i] = r;
                }
                __syncthreads();

                int ag = tid & 31, cg = tid >> 5;   // 8 col-groups of 4
                int lc = cg * 4, a0 = ag;
                float acc[4], rwin[4];
#pragma unroll
                for (int j = 0; j < 4; j++) { acc[j] = 0.f; rwin[j] = r_s[0][lc + j]; }
                for (int kb = 0; kb < KS; kb += 4) {
#pragma unroll
                    for (int ku = 0; ku < 4; ku++) {
                        int k = kb + ku;
                        float dv = d_s[k * 32 + a0];
#pragma unroll
                        for (int j = 0; j < 4; j++)
                            acc[j] = fmaf(dv, rwin[(ku + j) & 3], acc[j]);
                        rwin[ku] = r_s[0][lc + k + 4];
                    }
                }
                u64 b2 = 0ull;
#pragma unroll
                for (int j = 0; j < 4; j++) {
                    unsigned int f = (unsigned int)(abase + a0) * (unsigned int)T
                                   + (unsigned int)(t0 + lc + j);
                    u64 pm = packmax(acc[j], f);
                    if (pm > b2) b2 = pm;
                }
                b2 = warpmax(b2);
                if (lane == 0) wred[warp] = b2;
                __syncthreads();
                if (tid < 32) {
                    u64 v = (tid < 8) ? wred[tid] : 0ull;
                    v = warpmax(v);
                    if (tid == 0) stcg_u64(&bufW[hs * 4 + q], v);
                }
            }
            barrier_arrive(&flags[s * NBLK + bx]);
            barrier_wait(&flags[s * NBLK], NBLK);
        }
    }

    // ================= residual-norm partials =================
    if (bx < 32) {
        int base = bx * 512;
        float acc = 0.f;
        for (int t = base + tid; t < base + 512; t += NTHR) {
            float r = sig[t];
#pragma unroll
            for (int h = 0; h < STEPS; h++) {
                int j = t - sti[h] + 64;
                if ((unsigned)j < 128u) r -= sv[h] * g_dunit[sai[h] * KS + j];
            }
            acc = fmaf(r, r, acc);
        }
        shf[tid] = acc;
        __syncthreads();
        for (int off = 128; off; off >>= 1) {
            if (tid < off) shf[tid] += shf[tid + off];
            __syncthreads();
        }
        if (tid == 0) stcg_f32(&g_part[p][bx], shf[0]);
    }

    // ================= global barrier + final loss =================
    __syncthreads();
    __threadfence();
    if (tid == 0) st_release(&g_gflag[blockIdx.x], 1);
    if (blockIdx.x != 0) return;

    for (int f = tid; f < NBLK * NPROB; f += NTHR)
        while (ld_acquire(&g_gflag[f]) == 0) {}
    __threadfence();
    __syncthreads();

    // norms
    if (tid < NPROB) {
        float sum = 0.f;
        for (int i = 0; i < 32; i++) sum += ldcg_f32(&g_part[tid][i]);
        snorm[tid] = sqrtf(sum);
    }
    // ordering keys
    if (tid < 128) shf[tid] = proj[tid];
    __syncthreads();
    if (tid < NPROB * STEPS) {
        int pp = tid / STEPS, ss = tid % STEPS;
        const float* e = &g_embs[(pp * STEPS + ss) * 128];
        float k = 0.f;
        for (int c = 0; c < 128; c++) k = fmaf(ldcg_f32(&e[c]), shf[c], k);
        keys[pp][ss] = k;
    }
    __syncthreads();
    if (tid < NPROB * STEPS) {
        int pp = tid / STEPS, ss = tid % STEPS;
        float k = keys[pp][ss];
        int r = 0;
        for (int s2 = 0; s2 < STEPS; s2++) {
            float k2 = keys[pp][s2];
            if (k2 < k || (k2 == k && s2 < ss)) r++;
        }
        ord[pp][r] = ss;
    }
    __syncthreads();

    float acc = 0.f;
    if (tid < 128) {
        for (int pp = 0; pp < 2; pp++)
            for (int r = 0; r < STEPS; r++) {
                float da = ldcg_f32(&g_embs[(pp * STEPS + ord[pp][r]) * 128 + tid])
                         - ldcg_f32(&g_embs[((pp + 2) * STEPS + ord[pp + 2][r]) * 128 + tid]);
                acc = fmaf(da, da, acc);
            }
    }
    __syncthreads();
    shf[tid] = acc;
    __syncthreads();
    for (int off = 128; off; off >>= 1) {
        if (tid < off) shf[tid] += shf[tid + off];
        __syncthreads();
    }
    if (tid == 0) {
        float l1 = shf[0] / (float)(2 * STEPS * 128);
        float l2 = 0.5f * (fabsf(snorm[0] - snorm[2]) + fabsf(snorm[1] - snorm[3]));
        out[0] = l1 + l2;
    }
}

// ---------------- launch ----------------
extern "C" void kernel_launch(void* const* d_in, const int* in_sizes, int n_in,
                              void* d_out, int out_size) {
    const float* a    = (const float*)d_in[0];
    const float* b    = (const float*)d_in[1];
    const float* d    = (const float*)d_in[2];
    const float* aemb = (const float*)d_in[3];
    const float* proj = (const float*)d_in[4];
    float* out = (float*)d_out;

    k_dunit<<<A, 128>>>(d);
    k_persist<<<NPROB * NBLK, NTHR>>>(a, b, aemb, proj, out);
}